// round 1
// baseline (speedup 1.0000x reference)
#include <cuda_runtime.h>
#include <cuda_bf16.h>
#include <limits.h>

#define B     8
#define NN    1024
#define EE    1536
#define FIN   64
#define FOUT  64
#define FEDGE 32

// ---------------- scratch (static device globals; no allocation) ------------
__device__ int   g_emin[EE];
__device__ int   g_emax[EE];
__device__ float g_lw[EE];          // lap[src,dst] per edge
__device__ float g_lapii[NN];       // lap diagonal
__device__ float g_ew[B * EE];      // edge scalar weights
__device__ float g_S[B * NN];       // sum of ew over edges incident to node
__device__ float g_h[B * NN * FOUT];// nodes @ W

// K1: init scratch + gather lap diagonal
__global__ void k_init(const float* __restrict__ lap) {
    int t = blockIdx.x * blockDim.x + threadIdx.x;   // 8192 threads
    if (t < EE) { g_emin[t] = INT_MAX; g_emax[t] = -1; }
    if (t < NN) { g_lapii[t] = lap[t * NN + t]; }
    if (t < B * NN) { g_S[t] = 0.0f; }
}

// K2: recover edge endpoints from incidence matrix (coalesced float4 sweep)
__global__ void k_scan(const float4* __restrict__ inc4) {
    int t = blockIdx.x * blockDim.x + threadIdx.x;   // NN*EE/4 threads
    float4 v = inc4[t];
    int base = t * 4;
    int i = base / EE;
    int e = base % EE;
    if (v.x != 0.0f) { atomicMin(&g_emin[e + 0], i); atomicMax(&g_emax[e + 0], i); }
    if (v.y != 0.0f) { atomicMin(&g_emin[e + 1], i); atomicMax(&g_emax[e + 1], i); }
    if (v.z != 0.0f) { atomicMin(&g_emin[e + 2], i); atomicMax(&g_emax[e + 2], i); }
    if (v.w != 0.0f) { atomicMin(&g_emin[e + 3], i); atomicMax(&g_emax[e + 3], i); }
}

// K3: ew[b,e] = edges[b,e,:] . evec ; accumulate S at both endpoints; gather lap edge value
__global__ void k_edge(const float* __restrict__ edges,
                       const float* __restrict__ evec,
                       const float* __restrict__ lap) {
    int gw   = (blockIdx.x * blockDim.x + threadIdx.x) >> 5;  // warp per (b,e)
    int lane = threadIdx.x & 31;
    if (gw >= B * EE) return;
    int b = gw / EE, e = gw - b * EE;

    float x = edges[gw * FEDGE + lane] * evec[lane];
    #pragma unroll
    for (int o = 16; o; o >>= 1) x += __shfl_xor_sync(0xffffffffu, x, o);

    if (lane == 0) {
        int s = g_emin[e], d = g_emax[e];
        g_ew[gw] = x;
        atomicAdd(&g_S[b * NN + s], x);
        atomicAdd(&g_S[b * NN + d], x);
        if (b == 0) g_lw[e] = lap[s * NN + d];
    }
}

// K4: h = nodes @ W (smem-tiled), fused with diagonal term of the output:
//     out[b,i,c] = lapii[i] * S[b,i] * h[b,i,c]   (also stash h for K5)
__global__ void k_gemm_diag(const float* __restrict__ nodes,
                            const float* __restrict__ W,
                            float* __restrict__ out) {
    __shared__ float sW[FIN][FOUT];   // 16 KB
    __shared__ float sX[64][FIN];     // 16 KB, 64 rows per block
    int tid = threadIdx.x;            // 256
    int blk = blockIdx.x;             // 0..127 over flattened B*NN rows / 64

    const float* xrow = nodes + (size_t)blk * 64 * FIN;
    for (int k = tid; k < FIN * FOUT; k += 256) sW[k >> 6][k & 63] = W[k];
    for (int k = tid; k < 64 * FIN;   k += 256) sX[k >> 6][k & 63] = xrow[k];
    __syncthreads();

    int c  = tid & 63;       // output column
    int rg = tid >> 6;       // row group 0..3 (16 rows each)

    float acc[16];
    #pragma unroll
    for (int j = 0; j < 16; j++) acc[j] = 0.0f;

    #pragma unroll
    for (int k = 0; k < FIN; k++) {
        float w = sW[k][c];
        #pragma unroll
        for (int j = 0; j < 16; j++) acc[j] += sX[rg * 16 + j][k] * w;
    }

    #pragma unroll
    for (int j = 0; j < 16; j++) {
        int r = blk * 64 + rg * 16 + j;        // flattened b*NN + i
        float hv = acc[j];
        g_h[r * FOUT + c] = hv;
        out[r * FOUT + c] = g_lapii[r & (NN - 1)] * g_S[r] * hv;
    }
}

// K5: scatter off-diagonal edge contributions with fp32 atomics.
//     warp per (b,e); lane covers 2 feature channels (FOUT=64).
__global__ void k_scatter(float* __restrict__ out) {
    int gw   = (blockIdx.x * blockDim.x + threadIdx.x) >> 5;
    int lane = threadIdx.x & 31;
    if (gw >= B * EE) return;
    int b = gw / EE, e = gw - b * EE;

    float val = g_ew[gw] * g_lw[e];
    int s = g_emin[e], d = g_emax[e];

    const float* hs = g_h + (size_t)(b * NN + s) * FOUT;
    const float* hd = g_h + (size_t)(b * NN + d) * FOUT;
    float* os = out + (size_t)(b * NN + s) * FOUT;
    float* od = out + (size_t)(b * NN + d) * FOUT;

    atomicAdd(os + lane,      val * hd[lane]);
    atomicAdd(os + lane + 32, val * hd[lane + 32]);
    atomicAdd(od + lane,      val * hs[lane]);
    atomicAdd(od + lane + 32, val * hs[lane + 32]);
}

extern "C" void kernel_launch(void* const* d_in, const int* in_sizes, int n_in,
                              void* d_out, int out_size) {
    const float* nodes = (const float*)d_in[0];   // [B,N,FIN]
    const float* edges = (const float*)d_in[1];   // [B,E,FEDGE]
    const float* W     = (const float*)d_in[2];   // [FIN,FOUT]
    const float* evec  = (const float*)d_in[3];   // [FEDGE]
    const float* inc   = (const float*)d_in[4];   // [N,E]
    const float* lap   = (const float*)d_in[5];   // [N,N]
    float* out = (float*)d_out;                   // [B,N,FOUT]

    k_init<<<(B * NN + 255) / 256, 256>>>(lap);
    k_scan<<<(NN * EE / 4) / 256, 256>>>((const float4*)inc);
    k_edge<<<(B * EE * 32) / 256, 256>>>(edges, evec, lap);
    k_gemm_diag<<<(B * NN) / 64, 256>>>(nodes, W, out);
    k_scatter<<<(B * EE * 32) / 256, 256>>>(out);
}

// round 3
// speedup vs baseline: 1.3183x; 1.3183x over previous
#include <cuda_runtime.h>
#include <cuda_bf16.h>
#include <limits.h>

#define B     8
#define NN    1024
#define EE    1536
#define FIN   64
#define FOUT  64
#define FEDGE 32

// ---------------- scratch (static device globals; no allocation) ------------
__device__ int   g_emin[EE];
__device__ int   g_emax[EE];
__device__ float g_lw[EE];          // lap[src,dst] per edge
__device__ float g_lapii[NN];       // lap diagonal
__device__ float g_ew[B * EE];      // edge scalar weights
__device__ float g_S[B * NN];       // sum of ew over edges incident to node
__device__ float g_h[B * NN * FOUT];// nodes @ W

// K1: init scratch + gather lap diagonal
__global__ void k_init(const float* __restrict__ lap) {
    int t = blockIdx.x * blockDim.x + threadIdx.x;   // 8192 threads
    if (t < EE) { g_emin[t] = INT_MAX; g_emax[t] = -1; }
    if (t < NN) { g_lapii[t] = lap[t * NN + t]; }
    if (t < B * NN) { g_S[t] = 0.0f; }
}

// K2: recover edge endpoints from incidence matrix (coalesced float4 sweep)
__global__ void k_scan(const float4* __restrict__ inc4) {
    int t = blockIdx.x * blockDim.x + threadIdx.x;   // NN*EE/4 threads
    float4 v = inc4[t];
    int base = t * 4;
    int i = base / EE;
    int e = base % EE;
    if (v.x != 0.0f) { atomicMin(&g_emin[e + 0], i); atomicMax(&g_emax[e + 0], i); }
    if (v.y != 0.0f) { atomicMin(&g_emin[e + 1], i); atomicMax(&g_emax[e + 1], i); }
    if (v.z != 0.0f) { atomicMin(&g_emin[e + 2], i); atomicMax(&g_emax[e + 2], i); }
    if (v.w != 0.0f) { atomicMin(&g_emin[e + 3], i); atomicMax(&g_emax[e + 3], i); }
}

// K3: ew[b,e] = edges[b,e,:] . evec ; accumulate S at both endpoints; gather lap edge value
__global__ void k_edge(const float* __restrict__ edges,
                       const float* __restrict__ evec,
                       const float* __restrict__ lap) {
    int gw   = (blockIdx.x * blockDim.x + threadIdx.x) >> 5;  // warp per (b,e)
    int lane = threadIdx.x & 31;
    if (gw >= B * EE) return;
    int b = gw / EE, e = gw - b * EE;

    float x = edges[gw * FEDGE + lane] * evec[lane];
    #pragma unroll
    for (int o = 16; o; o >>= 1) x += __shfl_xor_sync(0xffffffffu, x, o);

    if (lane == 0) {
        int s = g_emin[e], d = g_emax[e];
        g_ew[gw] = x;
        atomicAdd(&g_S[b * NN + s], x);
        atomicAdd(&g_S[b * NN + d], x);
        if (b == 0) g_lw[e] = lap[s * NN + d];
    }
}

// K4 v2: h = nodes @ W with register tiling, fused diagonal output term.
// Block: 256 threads, 32 rows x 64 cols. Thread: 2 rows x 4 cols (float4 accs).
// 256 blocks (>=148 SMs), ~11KB unrolled body, LDS.128 on W, padded sX.
#define XPAD 68   // 32-row x-tile padded to 68 floats/row (16B aligned, conflict-free)
__global__ void __launch_bounds__(256) k_gemm_diag(const float* __restrict__ nodes,
                                                   const float* __restrict__ W,
                                                   float* __restrict__ out) {
    __shared__ float4 sW4[FIN][FOUT / 4];   // 16 KB, W[k][c] as float4 over c
    __shared__ float  sX[32][XPAD];         // ~8.5 KB

    int tid = threadIdx.x;                  // 256
    int blk = blockIdx.x;                   // 0..255, 32 rows each
    int R0  = blk * 32;

    // fill W tile: 1024 float4, 4 per thread (coalesced)
    const float4* W4 = (const float4*)W;
    #pragma unroll
    for (int i = 0; i < 4; i++) {
        int idx = tid + i * 256;            // 0..1023
        sW4[idx >> 4][idx & 15] = W4[idx];
    }
    // fill X tile: 32 rows x 64 floats = 512 float4, 2 per thread
    const float4* X4 = (const float4*)(nodes + (size_t)R0 * FIN);
    #pragma unroll
    for (int i = 0; i < 2; i++) {
        int idx = tid + i * 256;            // 0..511  -> row idx>>4, col4 idx&15
        float4 v = X4[idx];
        int row = idx >> 4, c4 = (idx & 15) * 4;
        sX[row][c4 + 0] = v.x; sX[row][c4 + 1] = v.y;
        sX[row][c4 + 2] = v.z; sX[row][c4 + 3] = v.w;
    }
    __syncthreads();

    int tx = tid & 15;        // col group: cols tx*4 .. tx*4+3
    int ty = tid >> 4;        // row group: rows ty*2, ty*2+1

    float4 a0 = make_float4(0.f, 0.f, 0.f, 0.f);
    float4 a1 = make_float4(0.f, 0.f, 0.f, 0.f);

    #pragma unroll
    for (int k = 0; k < FIN; k++) {
        float4 w  = sW4[k][tx];
        float  x0 = sX[ty * 2 + 0][k];
        float  x1 = sX[ty * 2 + 1][k];
        a0.x += x0 * w.x; a0.y += x0 * w.y; a0.z += x0 * w.z; a0.w += x0 * w.w;
        a1.x += x1 * w.x; a1.y += x1 * w.y; a1.z += x1 * w.z; a1.w += x1 * w.w;
    }

    int r0 = R0 + ty * 2;
    float d0 = g_lapii[r0 & (NN - 1)]       * g_S[r0];
    float d1 = g_lapii[(r0 + 1) & (NN - 1)] * g_S[r0 + 1];

    float4* gh4 = (float4*)g_h;
    float4* go4 = (float4*)out;
    int o0 = r0 * (FOUT / 4) + tx;
    int o1 = o0 + (FOUT / 4);

    gh4[o0] = a0;
    gh4[o1] = a1;
    go4[o0] = make_float4(d0 * a0.x, d0 * a0.y, d0 * a0.z, d0 * a0.w);
    go4[o1] = make_float4(d1 * a1.x, d1 * a1.y, d1 * a1.z, d1 * a1.w);
}

// K5: scatter off-diagonal edge contributions with fp32 atomics.
//     warp per (b,e); lane covers 2 feature channels (FOUT=64).
__global__ void k_scatter(float* __restrict__ out) {
    int gw   = (blockIdx.x * blockDim.x + threadIdx.x) >> 5;
    int lane = threadIdx.x & 31;
    if (gw >= B * EE) return;
    int b = gw / EE, e = gw - b * EE;

    float val = g_ew[gw] * g_lw[e];
    int s = g_emin[e], d = g_emax[e];

    const float* hs = g_h + (size_t)(b * NN + s) * FOUT;
    const float* hd = g_h + (size_t)(b * NN + d) * FOUT;
    float* os = out + (size_t)(b * NN + s) * FOUT;
    float* od = out + (size_t)(b * NN + d) * FOUT;

    atomicAdd(os + lane,      val * hd[lane]);
    atomicAdd(os + lane + 32, val * hd[lane + 32]);
    atomicAdd(od + lane,      val * hs[lane]);
    atomicAdd(od + lane + 32, val * hs[lane + 32]);
}

extern "C" void kernel_launch(void* const* d_in, const int* in_sizes, int n_in,
                              void* d_out, int out_size) {
    const float* nodes = (const float*)d_in[0];   // [B,N,FIN]
    const float* edges = (const float*)d_in[1];   // [B,E,FEDGE]
    const float* W     = (const float*)d_in[2];   // [FIN,FOUT]
    const float* evec  = (const float*)d_in[3];   // [FEDGE]
    const float* inc   = (const float*)d_in[4];   // [N,E]
    const float* lap   = (const float*)d_in[5];   // [N,N]
    float* out = (float*)d_out;                   // [B,N,FOUT]

    k_init<<<(B * NN + 255) / 256, 256>>>(lap);
    k_scan<<<(NN * EE / 4) / 256, 256>>>((const float4*)inc);
    k_edge<<<(B * EE * 32) / 256, 256>>>(edges, evec, lap);
    k_gemm_diag<<<(B * NN) / 32, 256>>>(nodes, W, out);
    k_scatter<<<(B * EE * 32) / 256, 256>>>(out);
}